// round 1
// baseline (speedup 1.0000x reference)
#include <cuda_runtime.h>
#include <cuda_bf16.h>

// Problem: B=8, D=3, N=M=4096.
// loss = mean((pred - chamfer(points, points_trans))^2), chamfer is [B,2]
// per-direction mean of min squared distance.
//
// Kernel 1: 256 blocks (b, dir, j-chunk) x 256 threads. Each thread owns 16
//   i-points (packed 2-wide into f32x2), scans a 256-point j chunk from smem,
//   keeps running min of (n2_j - 2*dot). Writes n1_i + min to scratch.
// Kernel 2: 16 blocks (b,dir): min over 16 chunks per i, mean over 4096 i.
// Kernel 3: 1 warp: MSE over 16 values -> d_out[0].

#define NPTS   4096
#define SPLITS 16
#define JCHUNK 256      // NPTS / SPLITS
#define TPB    256
#define IPER   16       // i-points per thread (8 packed pairs)

__device__ float g_partial[8 * 2 * SPLITS * NPTS];   // 8 MB scratch
__device__ float g_chamfer[16];

// ---- packed f32x2 helpers (sm_100+) ----
__device__ __forceinline__ unsigned long long pack2(float lo, float hi) {
    unsigned long long r;
    asm("mov.b64 %0, {%1, %2};" : "=l"(r) : "f"(lo), "f"(hi));
    return r;
}
__device__ __forceinline__ unsigned long long mul2(unsigned long long a, unsigned long long b) {
    unsigned long long r;
    asm("mul.rn.f32x2 %0, %1, %2;" : "=l"(r) : "l"(a), "l"(b));
    return r;
}
__device__ __forceinline__ unsigned long long fma2(unsigned long long a, unsigned long long b, unsigned long long c) {
    unsigned long long r;
    asm("fma.rn.f32x2 %0, %1, %2, %3;" : "=l"(r) : "l"(a), "l"(b), "l"(c));
    return r;
}
__device__ __forceinline__ void unpack2(unsigned long long v, float& lo, float& hi) {
    asm("mov.b64 {%0, %1}, %2;" : "=f"(lo), "=f"(hi) : "l"(v));
}

__global__ __launch_bounds__(TPB)
void chamfer_partial_kernel(const float* __restrict__ points,
                            const float* __restrict__ points_trans) {
    const int blk = blockIdx.x;          // 0..255
    const int s   = blk & (SPLITS - 1);  // j-chunk
    const int dir = (blk >> 4) & 1;
    const int b   = blk >> 5;

    const float* p1 = dir ? points_trans : points;
    const float* p2 = dir ? points : points_trans;
    const float* p1b = p1 + b * 3 * NPTS;
    const float* p2b = p2 + b * 3 * NPTS;

    __shared__ float4 sj[JCHUNK];

    const int t = threadIdx.x;

    // Load this block's j chunk: (x, y, z, |p|^2)
    {
        int j = s * JCHUNK + t;          // JCHUNK == TPB
        float x = p2b[j];
        float y = p2b[NPTS + j];
        float z = p2b[2 * NPTS + j];
        sj[t] = make_float4(x, y, z, x * x + y * y + z * z);
    }

    // Load this thread's 16 i-points and pack into f32x2 pairs.
    float x1[IPER], y1[IPER], z1[IPER];
#pragma unroll
    for (int k = 0; k < IPER; ++k) {
        int i = t + k * TPB;
        x1[k] = p1b[i];
        y1[k] = p1b[NPTS + i];
        z1[k] = p1b[2 * NPTS + i];
    }
    unsigned long long X[IPER / 2], Y[IPER / 2], Z[IPER / 2];
#pragma unroll
    for (int p = 0; p < IPER / 2; ++p) {
        X[p] = pack2(x1[2 * p], x1[2 * p + 1]);
        Y[p] = pack2(y1[2 * p], y1[2 * p + 1]);
        Z[p] = pack2(z1[2 * p], z1[2 * p + 1]);
    }

    float mn[IPER];
#pragma unroll
    for (int k = 0; k < IPER; ++k) mn[k] = 3.0e38f;

    const unsigned long long NEG2 = pack2(-2.0f, -2.0f);

    __syncthreads();

#pragma unroll 2
    for (int j = 0; j < JCHUNK; ++j) {
        float4 q = sj[j];                               // broadcast LDS.128
        unsigned long long x2 = pack2(q.x, q.x);
        unsigned long long y2 = pack2(q.y, q.y);
        unsigned long long z2 = pack2(q.z, q.z);
        unsigned long long n2 = pack2(q.w, q.w);
#pragma unroll
        for (int p = 0; p < IPER / 2; ++p) {
            unsigned long long c = mul2(X[p], x2);
            c = fma2(Y[p], y2, c);
            c = fma2(Z[p], z2, c);
            unsigned long long d = fma2(c, NEG2, n2);   // n2 - 2*dot
            float dlo, dhi;
            unpack2(d, dlo, dhi);
            mn[2 * p]     = fminf(mn[2 * p], dlo);
            mn[2 * p + 1] = fminf(mn[2 * p + 1], dhi);
        }
    }

    // partial[b][dir][s][i] = n1_i + min_j(n2_j - 2 c)
    float* dst = g_partial + ((size_t)((b * 2 + dir) * SPLITS + s)) * NPTS;
#pragma unroll
    for (int k = 0; k < IPER; ++k) {
        int i = t + k * TPB;
        float n1 = x1[k] * x1[k] + y1[k] * y1[k] + z1[k] * z1[k];
        dst[i] = n1 + mn[k];
    }
}

__global__ __launch_bounds__(TPB)
void chamfer_reduce_kernel() {
    const int bd = blockIdx.x;   // 0..15  (b*2 + dir)
    const int t  = threadIdx.x;

    float sum = 0.0f;
#pragma unroll
    for (int k = 0; k < IPER; ++k) {
        int i = t + k * TPB;
        float m = 3.0e38f;
        const float* src = g_partial + (size_t)bd * SPLITS * NPTS + i;
#pragma unroll
        for (int s = 0; s < SPLITS; ++s)
            m = fminf(m, src[s * NPTS]);
        sum += m;
    }

    __shared__ float red[TPB];
    red[t] = sum;
    __syncthreads();
    for (int off = TPB / 2; off >= 32; off >>= 1) {
        if (t < off) red[t] += red[t + off];
        __syncthreads();
    }
    if (t < 32) {
        float v = red[t];
#pragma unroll
        for (int off = 16; off > 0; off >>= 1)
            v += __shfl_xor_sync(0xFFFFFFFFu, v, off);
        if (t == 0) g_chamfer[bd] = v * (1.0f / (float)NPTS);
    }
}

__global__ void mse_kernel(const float* __restrict__ pred, float* __restrict__ out) {
    int t = threadIdx.x;
    float v = 0.0f;
    if (t < 16) {
        float d = pred[t] - g_chamfer[t];
        v = d * d;
    }
#pragma unroll
    for (int off = 16; off > 0; off >>= 1)
        v += __shfl_xor_sync(0xFFFFFFFFu, v, off);
    if (t == 0) out[0] = v * (1.0f / 16.0f);
}

extern "C" void kernel_launch(void* const* d_in, const int* in_sizes, int n_in,
                              void* d_out, int out_size) {
    const float* pred         = (const float*)d_in[0];   // [8,2]
    const float* points       = (const float*)d_in[1];   // [8,3,4096]
    const float* points_trans = (const float*)d_in[2];   // [8,3,4096]
    float* out = (float*)d_out;

    chamfer_partial_kernel<<<8 * 2 * SPLITS, TPB>>>(points, points_trans);
    chamfer_reduce_kernel<<<16, TPB>>>();
    mse_kernel<<<1, 32>>>(pred, out);
}

// round 2
// speedup vs baseline: 1.3065x; 1.3065x over previous
#include <cuda_runtime.h>
#include <cuda_bf16.h>

// B=8, D=3, N=M=4096 fused chamfer + MSE.
// Kernel 1: 2048 blocks = b(8) x dir(2) x i-split(4) x j-split(32), 256 thr.
//   f32x2 lanes carry a j-PAIR; i coords broadcast-packed once per thread.
//   Inner loop per j-pair per thread: 2 LDS.128 + 16 FMA2 + 8 FMNMX.
// Kernel 2: 128 blocks: min over 32 j-chunks, partial mean sums (deterministic).
// Kernel 3: 1 warp: finish means + MSE.

#define NPTS   4096
#define SPLITS 32            // j-splits
#define JCHUNK 128           // NPTS / SPLITS
#define JPAIRS (JCHUNK / 2)
#define ISPLITS 4
#define TPB    256
#define IPER   4             // i-points per thread (TPB*IPER = 1024 = NPTS/ISPLITS)

__device__ float g_partial[8 * 2 * SPLITS * NPTS];   // 8 MB scratch
__device__ float g_sums[16 * 8];                     // per (b,dir) x i-chunk sums

typedef unsigned long long u64;

__device__ __forceinline__ u64 pack2(float lo, float hi) {
    u64 r; asm("mov.b64 %0, {%1, %2};" : "=l"(r) : "f"(lo), "f"(hi)); return r;
}
__device__ __forceinline__ u64 mul2(u64 a, u64 b) {
    u64 r; asm("mul.rn.f32x2 %0, %1, %2;" : "=l"(r) : "l"(a), "l"(b)); return r;
}
__device__ __forceinline__ u64 fma2(u64 a, u64 b, u64 c) {
    u64 r; asm("fma.rn.f32x2 %0, %1, %2, %3;" : "=l"(r) : "l"(a), "l"(b), "l"(c)); return r;
}
__device__ __forceinline__ void unpack2(u64 v, float& lo, float& hi) {
    asm("mov.b64 {%0, %1}, %2;" : "=f"(lo), "=f"(hi) : "l"(v));
}
__device__ __forceinline__ void lds_v2u64(u64& a, u64& b, const void* p) {
    u64 g = __cvta_generic_to_shared(p);
    asm("ld.shared.v2.b64 {%0, %1}, [%2];" : "=l"(a), "=l"(b) : "l"(g));
}

__global__ __launch_bounds__(TPB, 4)
void chamfer_partial_kernel(const float* __restrict__ points,
                            const float* __restrict__ points_trans) {
    const int blk    = blockIdx.x;            // 0..2047
    const int s      = blk & (SPLITS - 1);    // j-chunk
    const int isplit = (blk >> 5) & (ISPLITS - 1);
    const int dir    = (blk >> 7) & 1;
    const int b      = blk >> 8;

    const float* p1b = (dir ? points_trans : points) + b * 3 * NPTS;
    const float* p2b = (dir ? points : points_trans) + b * 3 * NPTS;

    // smem: per j-pair, A = {x0,x1,y0,y1}, B = {z0,z1,n0,n1}
    __shared__ __align__(16) float sjA[JPAIRS * 4];
    __shared__ __align__(16) float sjB[JPAIRS * 4];

    const int t = threadIdx.x;

    if (t < JPAIRS) {
        int j = s * JCHUNK + 2 * t;
        float x0 = p2b[j],            x1 = p2b[j + 1];
        float y0 = p2b[NPTS + j],     y1 = p2b[NPTS + j + 1];
        float z0 = p2b[2 * NPTS + j], z1 = p2b[2 * NPTS + j + 1];
        sjA[4 * t + 0] = x0; sjA[4 * t + 1] = x1;
        sjA[4 * t + 2] = y0; sjA[4 * t + 3] = y1;
        sjB[4 * t + 0] = z0; sjB[4 * t + 1] = z1;
        sjB[4 * t + 2] = x0 * x0 + y0 * y0 + z0 * z0;
        sjB[4 * t + 3] = x1 * x1 + y1 * y1 + z1 * z1;
    }

    // Per-thread i points: broadcast-packed once.
    const int ibase = isplit * (TPB * IPER);
    u64 Xb[IPER], Yb[IPER], Zb[IPER];
    float n1[IPER];
#pragma unroll
    for (int k = 0; k < IPER; ++k) {
        int i = ibase + k * TPB + t;
        float x = p1b[i], y = p1b[NPTS + i], z = p1b[2 * NPTS + i];
        n1[k] = x * x + y * y + z * z;
        Xb[k] = pack2(x, x);
        Yb[k] = pack2(y, y);
        Zb[k] = pack2(z, z);
    }

    float mnlo[IPER], mnhi[IPER];
#pragma unroll
    for (int k = 0; k < IPER; ++k) { mnlo[k] = 3.0e38f; mnhi[k] = 3.0e38f; }

    const u64 NEG2 = pack2(-2.0f, -2.0f);

    __syncthreads();

#pragma unroll 4
    for (int jp = 0; jp < JPAIRS; ++jp) {
        u64 xj, yj, zj, nj;
        lds_v2u64(xj, yj, &sjA[4 * jp]);   // (x0,x1), (y0,y1)
        lds_v2u64(zj, nj, &sjB[4 * jp]);   // (z0,z1), (n0,n1)
#pragma unroll
        for (int k = 0; k < IPER; ++k) {
            u64 c = mul2(Xb[k], xj);
            c = fma2(Yb[k], yj, c);
            c = fma2(Zb[k], zj, c);
            u64 d = fma2(c, NEG2, nj);     // n2 - 2*dot, for (j0, j1)
            float dlo, dhi;
            unpack2(d, dlo, dhi);
            mnlo[k] = fminf(mnlo[k], dlo);
            mnhi[k] = fminf(mnhi[k], dhi);
        }
    }

    float* dst = g_partial + ((size_t)((b * 2 + dir) * SPLITS + s)) * NPTS;
#pragma unroll
    for (int k = 0; k < IPER; ++k) {
        int i = ibase + k * TPB + t;
        dst[i] = n1[k] + fminf(mnlo[k], mnhi[k]);
    }
}

__global__ __launch_bounds__(TPB)
void chamfer_reduce_kernel() {
    const int bd     = blockIdx.x >> 3;      // 0..15
    const int ichunk = blockIdx.x & 7;       // 0..7 (512 i each)
    const int t      = threadIdx.x;

    const float* base = g_partial + (size_t)bd * SPLITS * NPTS;
    float sum = 0.0f;
#pragma unroll
    for (int k = 0; k < 2; ++k) {
        int i = ichunk * 512 + k * TPB + t;
        float m = 3.0e38f;
#pragma unroll
        for (int s2 = 0; s2 < SPLITS; ++s2)
            m = fminf(m, base[s2 * NPTS + i]);
        sum += m;
    }

    __shared__ float red[TPB];
    red[t] = sum;
    __syncthreads();
    for (int off = TPB / 2; off >= 32; off >>= 1) {
        if (t < off) red[t] += red[t + off];
        __syncthreads();
    }
    if (t < 32) {
        float v = red[t];
#pragma unroll
        for (int off = 16; off > 0; off >>= 1)
            v += __shfl_xor_sync(0xFFFFFFFFu, v, off);
        if (t == 0) g_sums[bd * 8 + ichunk] = v;
    }
}

__global__ void mse_kernel(const float* __restrict__ pred, float* __restrict__ out) {
    int t = threadIdx.x;
    float v = 0.0f;
    if (t < 16) {
        float s = 0.0f;
#pragma unroll
        for (int c = 0; c < 8; ++c) s += g_sums[t * 8 + c];
        float cham = s * (1.0f / (float)NPTS);
        float d = pred[t] - cham;
        v = d * d;
    }
#pragma unroll
    for (int off = 16; off > 0; off >>= 1)
        v += __shfl_xor_sync(0xFFFFFFFFu, v, off);
    if (t == 0) out[0] = v * (1.0f / 16.0f);
}

extern "C" void kernel_launch(void* const* d_in, const int* in_sizes, int n_in,
                              void* d_out, int out_size) {
    const float* pred         = (const float*)d_in[0];   // [8,2]
    const float* points       = (const float*)d_in[1];   // [8,3,4096]
    const float* points_trans = (const float*)d_in[2];   // [8,3,4096]
    float* out = (float*)d_out;

    chamfer_partial_kernel<<<8 * 2 * ISPLITS * SPLITS, TPB>>>(points, points_trans);
    chamfer_reduce_kernel<<<128, TPB>>>();
    mse_kernel<<<1, 32>>>(pred, out);
}